// round 1
// baseline (speedup 1.0000x reference)
#include <cuda_runtime.h>

// Problem constants (fixed shapes from reference)
#define NN  100000
#define EE  1600000
#define FIN 512
#define C1  128    // 2*H
#define HH  64

// ---------------- scratch (no allocations allowed) ----------------
__device__ float g_t1[(size_t)NN * C1];   // x @ W1
__device__ float g_h [(size_t)NN * C1];   // relu(agg(t1) + b1)
__device__ float g_g [(size_t)NN * C1];   // agg(h)
__device__ float g_dinv[NN];
__device__ int   g_deg[NN];
__device__ int   g_rowptr[NN + 1];
__device__ int   g_cursor[NN];
__device__ int   g_srcs[EE];
__device__ int   g_partial[128];

// ---------------- graph preprocessing ----------------
__global__ void k_deg_init() {
    int i = blockIdx.x * blockDim.x + threadIdx.x;
    if (i < NN) g_deg[i] = 1;   // self-loop
}

__global__ void k_deg_count(const int* __restrict__ ei) {
    int e = blockIdx.x * blockDim.x + threadIdx.x;
    if (e < EE) atomicAdd(&g_deg[ei[EE + e]], 1);   // dst row of edge_index
}

__global__ void k_scan_local() {
    __shared__ int sd[1024];
    int t = threadIdx.x;
    int i = blockIdx.x * 1024 + t;
    int v = (i < NN) ? (g_deg[i] - 1) : 0;   // in-degree (excl. self-loop)
    sd[t] = v;
    __syncthreads();
#pragma unroll
    for (int off = 1; off < 1024; off <<= 1) {
        int x = (t >= off) ? sd[t - off] : 0;
        __syncthreads();
        sd[t] += x;
        __syncthreads();
    }
    if (i < NN) g_rowptr[i] = sd[t] - v;       // exclusive (local)
    if (t == 1023) g_partial[blockIdx.x] = sd[1023];
}

__global__ void k_scan_partials(int nb) {
    if (threadIdx.x == 0 && blockIdx.x == 0) {
        int s = 0;
        for (int b = 0; b < nb; b++) { int v = g_partial[b]; g_partial[b] = s; s += v; }
        g_rowptr[NN] = s;   // == EE
    }
}

__global__ void k_add_offsets() {
    int i = blockIdx.x * blockDim.x + threadIdx.x;
    if (i < NN) {
        int r = g_rowptr[i] + g_partial[i >> 10];
        g_rowptr[i] = r;
        g_cursor[i] = r;
        g_dinv[i] = rsqrtf((float)g_deg[i]);
    }
}

__global__ void k_scatter(const int* __restrict__ ei) {
    int e = blockIdx.x * blockDim.x + threadIdx.x;
    if (e < EE) {
        int s = ei[e];
        int d = ei[EE + e];
        int p = atomicAdd(&g_cursor[d], 1);
        g_srcs[p] = s;
    }
}

// ---------------- GEMM1: t1[N,128] = x[N,512] @ W1[512,128] ----------------
// BM=64 BN=128 BK=32, 256 threads, 4x8 microtile per thread
__global__ void k_gemm1(const float* __restrict__ x, const float* __restrict__ W) {
    __shared__ float xs[64][36];    // padded (stride 36) to avoid conflicts
    __shared__ float ws[32][128];

    int tid = threadIdx.x;
    int row_t = tid >> 4;   // 0..15 -> 4 rows each
    int col_t = tid & 15;   // 0..15 -> 8 cols each
    int block_row = blockIdx.x * 64;

    float acc[4][8];
#pragma unroll
    for (int i = 0; i < 4; i++)
#pragma unroll
        for (int j = 0; j < 8; j++) acc[i][j] = 0.f;

    for (int k0 = 0; k0 < FIN; k0 += 32) {
        // load x tile: 64x32 = 512 float4, 2 per thread
#pragma unroll
        for (int l = 0; l < 2; l++) {
            int f4 = tid * 2 + l;
            int r = f4 >> 3, c4 = f4 & 7;
            int grow = block_row + r;
            float4 v = make_float4(0.f, 0.f, 0.f, 0.f);
            if (grow < NN) v = *(const float4*)&x[(size_t)grow * FIN + k0 + c4 * 4];
            *(float4*)&xs[r][c4 * 4] = v;
        }
        // load W tile: 32x128 = 1024 float4, 4 per thread
#pragma unroll
        for (int l = 0; l < 4; l++) {
            int f4 = tid * 4 + l;
            int r = f4 >> 5, c4 = f4 & 31;
            *(float4*)&ws[r][c4 * 4] = *(const float4*)&W[(size_t)(k0 + r) * C1 + c4 * 4];
        }
        __syncthreads();
#pragma unroll
        for (int kk = 0; kk < 32; kk++) {
            float a0 = xs[row_t * 4 + 0][kk];
            float a1 = xs[row_t * 4 + 1][kk];
            float a2 = xs[row_t * 4 + 2][kk];
            float a3 = xs[row_t * 4 + 3][kk];
            float4 b0 = *(float4*)&ws[kk][col_t * 8];
            float4 b1 = *(float4*)&ws[kk][col_t * 8 + 4];
            float bb[8] = {b0.x, b0.y, b0.z, b0.w, b1.x, b1.y, b1.z, b1.w};
            float aa[4] = {a0, a1, a2, a3};
#pragma unroll
            for (int i = 0; i < 4; i++)
#pragma unroll
                for (int j = 0; j < 8; j++) acc[i][j] = fmaf(aa[i], bb[j], acc[i][j]);
        }
        __syncthreads();
    }
#pragma unroll
    for (int i = 0; i < 4; i++) {
        int r = block_row + row_t * 4 + i;
        if (r < NN) {
            float4 o0 = make_float4(acc[i][0], acc[i][1], acc[i][2], acc[i][3]);
            float4 o1 = make_float4(acc[i][4], acc[i][5], acc[i][6], acc[i][7]);
            *(float4*)&g_t1[(size_t)r * C1 + col_t * 8]     = o0;
            *(float4*)&g_t1[(size_t)r * C1 + col_t * 8 + 4] = o1;
        }
    }
}

// ---------------- aggregation: one warp per node, float4 per lane ----------------
// PASS 0: g_h = relu(agg(g_t1) + b1); PASS 1: g_g = agg(g_h)
template <int PASS>
__global__ void k_agg(const float* __restrict__ bias) {
    const float* __restrict__ in  = (PASS == 0) ? g_t1 : g_h;
    float* __restrict__ out       = (PASS == 0) ? g_h  : g_g;

    int warp = threadIdx.x >> 5;
    int lane = threadIdx.x & 31;
    int i = blockIdx.x * 4 + warp;
    if (i >= NN) return;

    float di = g_dinv[i];
    const float4* rowi = (const float4*)&in[(size_t)i * C1];
    float4 acc = rowi[lane];
    float sw = di * di;
    acc.x *= sw; acc.y *= sw; acc.z *= sw; acc.w *= sw;

    int e  = g_rowptr[i];
    int e1 = g_rowptr[i + 1];
    for (; e + 1 < e1; e += 2) {
        int s0 = g_srcs[e], s1 = g_srcs[e + 1];
        float w0 = g_dinv[s0] * di;
        float w1 = g_dinv[s1] * di;
        float4 v0 = *(const float4*)&in[(size_t)s0 * C1 + lane * 4];
        float4 v1 = *(const float4*)&in[(size_t)s1 * C1 + lane * 4];
        acc.x = fmaf(v0.x, w0, fmaf(v1.x, w1, acc.x));
        acc.y = fmaf(v0.y, w0, fmaf(v1.y, w1, acc.y));
        acc.z = fmaf(v0.z, w0, fmaf(v1.z, w1, acc.z));
        acc.w = fmaf(v0.w, w0, fmaf(v1.w, w1, acc.w));
    }
    if (e < e1) {
        int s0 = g_srcs[e];
        float w0 = g_dinv[s0] * di;
        float4 v0 = *(const float4*)&in[(size_t)s0 * C1 + lane * 4];
        acc.x = fmaf(v0.x, w0, acc.x);
        acc.y = fmaf(v0.y, w0, acc.y);
        acc.z = fmaf(v0.z, w0, acc.z);
        acc.w = fmaf(v0.w, w0, acc.w);
    }
    if (PASS == 0) {
        float4 b = *(const float4*)&bias[lane * 4];
        acc.x = fmaxf(acc.x + b.x, 0.f);
        acc.y = fmaxf(acc.y + b.y, 0.f);
        acc.z = fmaxf(acc.z + b.z, 0.f);
        acc.w = fmaxf(acc.w + b.w, 0.f);
    }
    *(float4*)&out[(size_t)i * C1 + lane * 4] = acc;
}

// ---------------- GEMM2: [mu | logstd] = g[N,128] @ [Wmu|Wls][128,128] + bias ----
__global__ void k_gemm2(const float* __restrict__ Wmu, const float* __restrict__ Wls,
                        const float* __restrict__ bmu, const float* __restrict__ bls,
                        float* __restrict__ out) {
    __shared__ float as_[64][36];
    __shared__ float ws[32][128];

    int tid = threadIdx.x;
    int row_t = tid >> 4;
    int col_t = tid & 15;
    int block_row = blockIdx.x * 64;

    float acc[4][8];
#pragma unroll
    for (int i = 0; i < 4; i++)
#pragma unroll
        for (int j = 0; j < 8; j++) acc[i][j] = 0.f;

    for (int k0 = 0; k0 < C1; k0 += 32) {
#pragma unroll
        for (int l = 0; l < 2; l++) {
            int f4 = tid * 2 + l;
            int r = f4 >> 3, c4 = f4 & 7;
            int grow = block_row + r;
            float4 v = make_float4(0.f, 0.f, 0.f, 0.f);
            if (grow < NN) v = *(const float4*)&g_g[(size_t)grow * C1 + k0 + c4 * 4];
            *(float4*)&as_[r][c4 * 4] = v;
        }
#pragma unroll
        for (int l = 0; l < 16; l++) {
            int idx = tid + 256 * l;
            int r = idx >> 7, c = idx & 127;
            float v = (c < 64) ? Wmu[(size_t)(k0 + r) * HH + c]
                               : Wls[(size_t)(k0 + r) * HH + (c - 64)];
            ws[r][c] = v;
        }
        __syncthreads();
#pragma unroll
        for (int kk = 0; kk < 32; kk++) {
            float aa[4];
#pragma unroll
            for (int i = 0; i < 4; i++) aa[i] = as_[row_t * 4 + i][kk];
            float4 b0 = *(float4*)&ws[kk][col_t * 8];
            float4 b1 = *(float4*)&ws[kk][col_t * 8 + 4];
            float bb[8] = {b0.x, b0.y, b0.z, b0.w, b1.x, b1.y, b1.z, b1.w};
#pragma unroll
            for (int i = 0; i < 4; i++)
#pragma unroll
                for (int j = 0; j < 8; j++) acc[i][j] = fmaf(aa[i], bb[j], acc[i][j]);
        }
        __syncthreads();
    }
    // epilogue: col_t<8 -> mu half; col_t>=8 -> logstd half
    bool isls = (col_t >= 8);
    int cbase = (col_t & 7) * 8;
    const float* bias = isls ? bls : bmu;
    float* dst = out + (isls ? (size_t)NN * HH : 0);
    float bv[8];
#pragma unroll
    for (int j = 0; j < 8; j++) bv[j] = bias[cbase + j];
#pragma unroll
    for (int i = 0; i < 4; i++) {
        int r = block_row + row_t * 4 + i;
        if (r < NN) {
            float4 o0 = make_float4(acc[i][0] + bv[0], acc[i][1] + bv[1],
                                    acc[i][2] + bv[2], acc[i][3] + bv[3]);
            float4 o1 = make_float4(acc[i][4] + bv[4], acc[i][5] + bv[5],
                                    acc[i][6] + bv[6], acc[i][7] + bv[7]);
            *(float4*)&dst[(size_t)r * HH + cbase]     = o0;
            *(float4*)&dst[(size_t)r * HH + cbase + 4] = o1;
        }
    }
}

// ---------------- launch ----------------
extern "C" void kernel_launch(void* const* d_in, const int* in_sizes, int n_in,
                              void* d_out, int out_size) {
    const float* x   = (const float*)d_in[0];
    const int*   ei  = (const int*)d_in[1];
    const float* W1  = (const float*)d_in[2];
    const float* b1  = (const float*)d_in[3];
    const float* Wmu = (const float*)d_in[4];
    const float* bmu = (const float*)d_in[5];
    const float* Wls = (const float*)d_in[6];
    const float* bls = (const float*)d_in[7];
    float* out = (float*)d_out;

    const int nb_n = (NN + 255) / 256;
    const int nb_e = (EE + 255) / 256;
    const int nb_s = (NN + 1023) / 1024;   // 98

    k_deg_init<<<nb_n, 256>>>();
    k_deg_count<<<nb_e, 256>>>(ei);
    k_scan_local<<<nb_s, 1024>>>();
    k_scan_partials<<<1, 32>>>(nb_s);
    k_add_offsets<<<nb_n, 256>>>();
    k_scatter<<<nb_e, 256>>>(ei);

    k_gemm1<<<(NN + 63) / 64, 256>>>(x, W1);
    k_agg<0><<<(NN + 3) / 4, 128>>>(b1);
    k_agg<1><<<(NN + 3) / 4, 128>>>(nullptr);
    k_gemm2<<<(NN + 63) / 64, 256>>>(Wmu, Wls, bmu, bls, out);
}

// round 3
// speedup vs baseline: 1.8781x; 1.8781x over previous
#include <cuda_runtime.h>
#include <cuda_bf16.h>
#include <cstdint>

#define NN  100000
#define EE  1600000
#define FIN 512
#define C1  128    // 2*H
#define HH  64

// ---------------- scratch (no allocations allowed) ----------------
__device__ float g_t1[(size_t)NN * C1];   // x @ W1
__device__ float g_h [(size_t)NN * C1];   // relu(agg(t1) + b1)
__device__ float g_g [(size_t)NN * C1];   // agg(h)
__device__ float g_dinv[NN];
__device__ int   g_deg[NN];
__device__ int   g_rowptr[NN + 1];
__device__ int   g_cursor[NN];
__device__ int   g_srcs[EE];
__device__ int   g_partial[128];
// W1 split into bf16 hi/lo, row-major [k=512][n=128]
__device__ __align__(16) __nv_bfloat16 g_whi[FIN * C1];
__device__ __align__(16) __nv_bfloat16 g_wlo[FIN * C1];

// ---------------- helpers ----------------
__device__ __forceinline__ uint32_t smem_u32(const void* p) {
    uint32_t a;
    asm("{ .reg .u64 t; cvta.to.shared.u64 t, %1; cvt.u32.u64 %0, t; }" : "=r"(a) : "l"(p));
    return a;
}
__device__ __forceinline__ uint32_t bfpack(float a, float b) {
    __nv_bfloat162 t = __floats2bfloat162_rn(a, b);
    return *reinterpret_cast<uint32_t*>(&t);
}
__device__ __forceinline__ void ldsm_x4(uint32_t& r0, uint32_t& r1, uint32_t& r2, uint32_t& r3,
                                        uint32_t addr) {
    asm volatile("ldmatrix.sync.aligned.m8n8.x4.shared.b16 {%0,%1,%2,%3}, [%4];"
                 : "=r"(r0), "=r"(r1), "=r"(r2), "=r"(r3) : "r"(addr));
}
__device__ __forceinline__ void ldsm_x4_t(uint32_t& r0, uint32_t& r1, uint32_t& r2, uint32_t& r3,
                                          uint32_t addr) {
    asm volatile("ldmatrix.sync.aligned.m8n8.x4.trans.shared.b16 {%0,%1,%2,%3}, [%4];"
                 : "=r"(r0), "=r"(r1), "=r"(r2), "=r"(r3) : "r"(addr));
}
__device__ __forceinline__ void mma_bf16(float* c, const uint32_t* a, const uint32_t* b) {
    asm volatile(
        "mma.sync.aligned.m16n8k16.row.col.f32.bf16.bf16.f32 "
        "{%0,%1,%2,%3}, {%4,%5,%6,%7}, {%8,%9}, {%0,%1,%2,%3};"
        : "+f"(c[0]), "+f"(c[1]), "+f"(c[2]), "+f"(c[3])
        : "r"(a[0]), "r"(a[1]), "r"(a[2]), "r"(a[3]), "r"(b[0]), "r"(b[1]));
}

// ---------------- W1 preprocessing: fp32 -> bf16 hi/lo --------------------
__global__ void k_prep_w(const float* __restrict__ W1) {
    int idx = blockIdx.x * 256 + threadIdx.x;   // k*128+n
    if (idx >= FIN * C1) return;
    float w = W1[idx];
    __nv_bfloat16 hi = __float2bfloat16(w);
    g_whi[idx] = hi;
    g_wlo[idx] = __float2bfloat16(w - __bfloat162float(hi));
}

// ---------------- graph preprocessing ----------------
__global__ void k_deg_init() {
    int i = blockIdx.x * blockDim.x + threadIdx.x;
    if (i < NN) g_deg[i] = 1;   // self-loop
}

__global__ void k_deg_count(const int* __restrict__ ei) {
    int e = blockIdx.x * blockDim.x + threadIdx.x;
    if (e < EE) atomicAdd(&g_deg[ei[EE + e]], 1);   // dst row
}

__global__ void k_scan_local() {
    __shared__ int sd[1024];
    int t = threadIdx.x;
    int i = blockIdx.x * 1024 + t;
    int v = (i < NN) ? (g_deg[i] - 1) : 0;
    sd[t] = v;
    __syncthreads();
#pragma unroll
    for (int off = 1; off < 1024; off <<= 1) {
        int x = (t >= off) ? sd[t - off] : 0;
        __syncthreads();
        sd[t] += x;
        __syncthreads();
    }
    if (i < NN) g_rowptr[i] = sd[t] - v;
    if (t == 1023) g_partial[blockIdx.x] = sd[1023];   // raw block totals
}

__global__ void k_add_offsets() {
    __shared__ int base;
    int i = blockIdx.x * 256 + threadIdx.x;
    if (threadIdx.x == 0) {
        int nb = blockIdx.x >> 2;
        int s = 0;
        for (int b = 0; b < nb; b++) s += g_partial[b];
        base = s;
    }
    __syncthreads();
    if (i < NN) {
        int r = g_rowptr[i] + base;
        g_rowptr[i] = r;
        g_cursor[i] = r;
        g_dinv[i] = rsqrtf((float)g_deg[i]);
    }
    if (i == 0) g_rowptr[NN] = EE;
}

__global__ void k_scatter(const int* __restrict__ ei) {
    int e = blockIdx.x * blockDim.x + threadIdx.x;
    if (e < EE) {
        int s = ei[e];
        int d = ei[EE + e];
        int p = atomicAdd(&g_cursor[d], 1);
        g_srcs[p] = s;
    }
}

// ---------------- GEMM1 (mma.sync bf16, 3-term split) ---------------------
// t1[N,128] = x[N,512] @ W1[512,128];  CTA: 128x128, 8 warps (4x2), warp 32x64.
// K chunks of 32 staged in smem; A rows padded to 80B, W rows to 272B.
#define A_STRIDE 80      // bytes per A smem row (32 bf16 = 64B + 16B pad)
#define W_STRIDE 272     // bytes per W smem row (128 bf16 = 256B + 16B pad)

__global__ void __launch_bounds__(256, 2)
k_gemm1_mma(const float* __restrict__ x) {
    __shared__ __align__(16) unsigned char sAh[128 * A_STRIDE];
    __shared__ __align__(16) unsigned char sAl[128 * A_STRIDE];
    __shared__ __align__(16) unsigned char sWh[32 * W_STRIDE];
    __shared__ __align__(16) unsigned char sWl[32 * W_STRIDE];

    const int tid = threadIdx.x;
    const int wid = tid >> 5, lane = tid & 31;
    const int warp_m = wid & 3;        // 0..3 -> rows warp_m*32
    const int warp_n = wid >> 2;       // 0..1 -> cols warp_n*64
    const int block_row = blockIdx.x * 128;

    const uint32_t sAh_u = smem_u32(sAh), sAl_u = smem_u32(sAl);
    const uint32_t sWh_u = smem_u32(sWh), sWl_u = smem_u32(sWl);

    float c[2][8][4];
#pragma unroll
    for (int mi = 0; mi < 2; mi++)
#pragma unroll
        for (int ni = 0; ni < 8; ni++)
#pragma unroll
            for (int q = 0; q < 4; q++) c[mi][ni][q] = 0.f;

    // ldmatrix lane addressing (shared across tiles)
    const int lrow = lane & 15;
    const int lcol16 = (lane >> 4) * 16;   // byte offset for second 8-col group

    for (int kc = 0; kc < FIN / 32; kc++) {
        // ---- stage A (fp32 -> bf16 hi/lo): 128x32, 1024 float4, 4/thread ----
#pragma unroll
        for (int l = 0; l < 4; l++) {
            int f4 = tid + 256 * l;
            int r = f4 >> 3, c4 = f4 & 7;
            int grow = block_row + r;
            float4 v = make_float4(0.f, 0.f, 0.f, 0.f);
            if (grow < NN) v = *(const float4*)&x[(size_t)grow * FIN + kc * 32 + c4 * 4];
            float hx = __bfloat162float(__float2bfloat16(v.x));
            float hy = __bfloat162float(__float2bfloat16(v.y));
            float hz = __bfloat162float(__float2bfloat16(v.z));
            float hw = __bfloat162float(__float2bfloat16(v.w));
            uint2 hi = make_uint2(bfpack(v.x, v.y), bfpack(v.z, v.w));
            uint2 lo = make_uint2(bfpack(v.x - hx, v.y - hy), bfpack(v.z - hz, v.w - hw));
            *(uint2*)(sAh + r * A_STRIDE + c4 * 8) = hi;
            *(uint2*)(sAl + r * A_STRIDE + c4 * 8) = lo;
        }
        // ---- stage W hi/lo: 32x128 bf16 each; 512 uint4 per matrix, 2/thread ----
#pragma unroll
        for (int l = 0; l < 2; l++) {
            int u4 = tid + 256 * l;
            int r = u4 >> 4, c16 = u4 & 15;     // 16 uint4 per row
            *(uint4*)(sWh + r * W_STRIDE + c16 * 16) =
                *(const uint4*)&g_whi[(size_t)(kc * 32 + r) * C1 + c16 * 8];
            *(uint4*)(sWl + r * W_STRIDE + c16 * 16) =
                *(const uint4*)&g_wlo[(size_t)(kc * 32 + r) * C1 + c16 * 8];
        }
        __syncthreads();

#pragma unroll
        for (int slab = 0; slab < 2; slab++) {      // two k16 slabs per chunk
            // A fragments for this warp: 2 m16 tiles, hi and lo
            uint32_t ah[2][4], al[2][4];
#pragma unroll
            for (int mi = 0; mi < 2; mi++) {
                uint32_t aoff = (uint32_t)(warp_m * 32 + mi * 16 + lrow) * A_STRIDE
                              + slab * 32 + lcol16;
                ldsm_x4(ah[mi][0], ah[mi][1], ah[mi][2], ah[mi][3], sAh_u + aoff);
                ldsm_x4(al[mi][0], al[mi][1], al[mi][2], al[mi][3], sAl_u + aoff);
            }
            // process warp's 64 cols in two n32 halves to bound live registers
#pragma unroll
            for (int h = 0; h < 2; h++) {
                uint32_t bh[4][2], bl[4][2];
#pragma unroll
                for (int q = 0; q < 2; q++) {   // q: n16 group
                    uint32_t boff = (uint32_t)(slab * 16 + lrow) * W_STRIDE
                                  + (warp_n * 64 + h * 32 + q * 16) * 2 + lcol16;
                    ldsm_x4_t(bh[q * 2][0], bh[q * 2][1], bh[q * 2 + 1][0], bh[q * 2 + 1][1],
                              sWh_u + boff);
                    ldsm_x4_t(bl[q * 2][0], bl[q * 2][1], bl[q * 2 + 1][0], bl[q * 2 + 1][1],
                              sWl_u + boff);
                }
#pragma unroll
                for (int mi = 0; mi < 2; mi++)
#pragma unroll
                    for (int nn = 0; nn < 4; nn++) {
                        float* cc = c[mi][h * 4 + nn];
                        mma_bf16(cc, ah[mi], bh[nn]);
                        mma_bf16(cc, al[mi], bh[nn]);
                        mma_bf16(cc, ah[mi], bl[nn]);
                    }
            }
        }
        __syncthreads();
    }

    // ---- epilogue: c[mi][ni][q] -> g_t1 ----
    const int qrow = lane >> 2;             // 0..7
    const int qcol = (lane & 3) * 2;        // 0,2,4,6
#pragma unroll
    for (int mi = 0; mi < 2; mi++) {
        int r0 = block_row + warp_m * 32 + mi * 16 + qrow;
#pragma unroll
        for (int ni = 0; ni < 8; ni++) {
            int col = warp_n * 64 + ni * 8 + qcol;
            if (r0 < NN)
                *(float2*)&g_t1[(size_t)r0 * C1 + col] = make_float2(c[mi][ni][0], c[mi][ni][1]);
            if (r0 + 8 < NN)
                *(float2*)&g_t1[(size_t)(r0 + 8) * C1 + col] = make_float2(c[mi][ni][2], c[mi][ni][3]);
        }
    }
}

// ---------------- aggregation: one warp per node, float4 per lane ----------------
template <int PASS>
__global__ void k_agg(const float* __restrict__ bias) {
    const float* __restrict__ in  = (PASS == 0) ? g_t1 : g_h;
    float* __restrict__ out       = (PASS == 0) ? g_h  : g_g;

    int warp = threadIdx.x >> 5;
    int lane = threadIdx.x & 31;
    int i = blockIdx.x * 4 + warp;
    if (i >= NN) return;

    float di = g_dinv[i];
    const float4* rowi = (const float4*)&in[(size_t)i * C1];
    float4 acc = rowi[lane];
    float sw = di * di;
    acc.x *= sw; acc.y *= sw; acc.z *= sw; acc.w *= sw;

    int e  = g_rowptr[i];
    int e1 = g_rowptr[i + 1];
    for (; e + 1 < e1; e += 2) {
        int s0 = g_srcs[e], s1 = g_srcs[e + 1];
        float w0 = g_dinv[s0] * di;
        float w1 = g_dinv[s1] * di;
        float4 v0 = *(const float4*)&in[(size_t)s0 * C1 + lane * 4];
        float4 v1 = *(const float4*)&in[(size_t)s1 * C1 + lane * 4];
        acc.x = fmaf(v0.x, w0, fmaf(v1.x, w1, acc.x));
        acc.y = fmaf(v0.y, w0, fmaf(v1.y, w1, acc.y));
        acc.z = fmaf(v0.z, w0, fmaf(v1.z, w1, acc.z));
        acc.w = fmaf(v0.w, w0, fmaf(v1.w, w1, acc.w));
    }
    if (e < e1) {
        int s0 = g_srcs[e];
        float w0 = g_dinv[s0] * di;
        float4 v0 = *(const float4*)&in[(size_t)s0 * C1 + lane * 4];
        acc.x = fmaf(v0.x, w0, acc.x);
        acc.y = fmaf(v0.y, w0, acc.y);
        acc.z = fmaf(v0.z, w0, acc.z);
        acc.w = fmaf(v0.w, w0, acc.w);
    }
    if (PASS == 0) {
        float4 b = *(const float4*)&bias[lane * 4];
        acc.x = fmaxf(acc.x + b.x, 0.f);
        acc.y = fmaxf(acc.y + b.y, 0.f);
        acc.z = fmaxf(acc.z + b.z, 0.f);
        acc.w = fmaxf(acc.w + b.w, 0.f);
    }
    *(float4*)&out[(size_t)i * C1 + lane * 4] = acc;
}

// ---------------- GEMM2: [mu | logstd] = g[N,128] @ [Wmu|Wls][128,128] + bias ----
__global__ void k_gemm2(const float* __restrict__ Wmu, const float* __restrict__ Wls,
                        const float* __restrict__ bmu, const float* __restrict__ bls,
                        float* __restrict__ out) {
    __shared__ float as_[64][36];
    __shared__ float ws[32][128];

    int tid = threadIdx.x;
    int row_t = tid >> 4;
    int col_t = tid & 15;
    int block_row = blockIdx.x * 64;

    float acc[4][8];
#pragma unroll
    for (int i = 0; i < 4; i++)
#pragma unroll
        for (int j = 0; j < 8; j++) acc[i][j] = 0.f;

    for (int k0 = 0; k0 < C1; k0 += 32) {
#pragma unroll
        for (int l = 0; l < 2; l++) {
            int f4 = tid * 2 + l;
            int r = f4 >> 3, c4 = f4 & 7;
            int grow = block_row + r;
            float4 v = make_float4(0.f, 0.f, 0.f, 0.f);
            if (grow < NN) v = *(const float4*)&g_g[(size_t)grow * C1 + k0 + c4 * 4];
            *(float4*)&as_[r][c4 * 4] = v;
        }
#pragma unroll
        for (int l = 0; l < 16; l++) {
            int idx = tid + 256 * l;
            int r = idx >> 7, c = idx & 127;
            float v = (c < 64) ? Wmu[(size_t)(k0 + r) * HH + c]
                               : Wls[(size_t)(k0 + r) * HH + (c - 64)];
            ws[r][c] = v;
        }
        __syncthreads();
#pragma unroll
        for (int kk = 0; kk < 32; kk++) {
            float aa[4];
#pragma unroll
            for (int i = 0; i < 4; i++) aa[i] = as_[row_t * 4 + i][kk];
            float4 b0 = *(float4*)&ws[kk][col_t * 8];
            float4 b1 = *(float4*)&ws[kk][col_t * 8 + 4];
            float bb[8] = {b0.x, b0.y, b0.z, b0.w, b1.x, b1.y, b1.z, b1.w};
#pragma unroll
            for (int i = 0; i < 4; i++)
#pragma unroll
                for (int j = 0; j < 8; j++) acc[i][j] = fmaf(aa[i], bb[j], acc[i][j]);
        }
        __syncthreads();
    }
    bool isls = (col_t >= 8);
    int cbase = (col_t & 7) * 8;
    const float* bias = isls ? bls : bmu;
    float* dst = out + (isls ? (size_t)NN * HH : 0);
    float bv[8];
#pragma unroll
    for (int j = 0; j < 8; j++) bv[j] = bias[cbase + j];
#pragma unroll
    for (int i = 0; i < 4; i++) {
        int r = block_row + row_t * 4 + i;
        if (r < NN) {
            float4 o0 = make_float4(acc[i][0] + bv[0], acc[i][1] + bv[1],
                                    acc[i][2] + bv[2], acc[i][3] + bv[3]);
            float4 o1 = make_float4(acc[i][4] + bv[4], acc[i][5] + bv[5],
                                    acc[i][6] + bv[6], acc[i][7] + bv[7]);
            *(float4*)&dst[(size_t)r * HH + cbase]     = o0;
            *(float4*)&dst[(size_t)r * HH + cbase + 4] = o1;
        }
    }
}

// ---------------- launch ----------------
extern "C" void kernel_launch(void* const* d_in, const int* in_sizes, int n_in,
                              void* d_out, int out_size) {
    const float* x   = (const float*)d_in[0];
    const int*   ei  = (const int*)d_in[1];
    const float* W1  = (const float*)d_in[2];
    const float* b1  = (const float*)d_in[3];
    const float* Wmu = (const float*)d_in[4];
    const float* bmu = (const float*)d_in[5];
    const float* Wls = (const float*)d_in[6];
    const float* bls = (const float*)d_in[7];
    float* out = (float*)d_out;

    const int nb_n = (NN + 255) / 256;
    const int nb_e = (EE + 255) / 256;
    const int nb_s = (NN + 1023) / 1024;

    k_prep_w<<<(FIN * C1 + 255) / 256, 256>>>(W1);
    k_deg_init<<<nb_n, 256>>>();
    k_deg_count<<<nb_e, 256>>>(ei);
    k_gemm1_mma<<<(NN + 127) / 128, 256>>>(x);
    k_scan_local<<<nb_s, 1024>>>();
    k_add_offsets<<<nb_n, 256>>>();
    k_scatter<<<nb_e, 256>>>(ei);

    k_agg<0><<<(NN + 3) / 4, 128>>>(b1);
    k_agg<1><<<(NN + 3) / 4, 128>>>(nullptr);
    k_gemm2<<<(NN + 63) / 64, 256>>>(Wmu, Wls, bmu, bls, out);
}

// round 7
// speedup vs baseline: 2.6181x; 1.3940x over previous
#include <cuda_runtime.h>
#include <cuda_bf16.h>
#include <cstdint>

#define NN  100000
#define EE  1600000
#define FIN 512
#define C1  128    // 2*H
#define HH  64

// ---------------- scratch (no allocations allowed) ----------------
__device__ float g_t1[(size_t)NN * C1];   // x @ W1
__device__ float g_h [(size_t)NN * C1];   // relu(agg(t1) + b1)
__device__ float g_p [(size_t)NN * C1];   // h @ [Wmu|Wls]
__device__ float g_dinv[NN];
__device__ int   g_deg[NN];
__device__ int   g_rowptr[NN + 1];
__device__ int   g_cursor[NN];
__device__ int   g_srcs[EE];
__device__ int   g_partial[128];
// weights split into bf16 hi/lo, row-major [k][n=128]
__device__ __align__(16) __nv_bfloat16 g_whi[FIN * C1];
__device__ __align__(16) __nv_bfloat16 g_wlo[FIN * C1];
__device__ __align__(16) __nv_bfloat16 g_wchi[C1 * C1];
__device__ __align__(16) __nv_bfloat16 g_wclo[C1 * C1];

// ---------------- helpers ----------------
__device__ __forceinline__ uint32_t smem_u32(const void* p) {
    uint32_t a;
    asm("{ .reg .u64 t; cvta.to.shared.u64 t, %1; cvt.u32.u64 %0, t; }" : "=r"(a) : "l"(p));
    return a;
}
__device__ __forceinline__ uint32_t bfpack(float a, float b) {
    __nv_bfloat162 t = __floats2bfloat162_rn(a, b);
    return *reinterpret_cast<uint32_t*>(&t);
}
__device__ __forceinline__ void ldsm_x4(uint32_t& r0, uint32_t& r1, uint32_t& r2, uint32_t& r3,
                                        uint32_t addr) {
    asm volatile("ldmatrix.sync.aligned.m8n8.x4.shared.b16 {%0,%1,%2,%3}, [%4];"
                 : "=r"(r0), "=r"(r1), "=r"(r2), "=r"(r3) : "r"(addr));
}
__device__ __forceinline__ void ldsm_x4_t(uint32_t& r0, uint32_t& r1, uint32_t& r2, uint32_t& r3,
                                          uint32_t addr) {
    asm volatile("ldmatrix.sync.aligned.m8n8.x4.trans.shared.b16 {%0,%1,%2,%3}, [%4];"
                 : "=r"(r0), "=r"(r1), "=r"(r2), "=r"(r3) : "r"(addr));
}
__device__ __forceinline__ void mma_bf16(float* c, const uint32_t* a, const uint32_t* b) {
    asm volatile(
        "mma.sync.aligned.m16n8k16.row.col.f32.bf16.bf16.f32 "
        "{%0,%1,%2,%3}, {%4,%5,%6,%7}, {%8,%9}, {%0,%1,%2,%3};"
        : "+f"(c[0]), "+f"(c[1]), "+f"(c[2]), "+f"(c[3])
        : "r"(a[0]), "r"(a[1]), "r"(a[2]), "r"(a[3]), "r"(b[0]), "r"(b[1]));
}

// ---------------- weight preprocessing: fp32 -> bf16 hi/lo ----------------
__global__ void k_prep_w(const float* __restrict__ W1,
                         const float* __restrict__ Wmu, const float* __restrict__ Wls) {
    int idx = blockIdx.x * 256 + threadIdx.x;
    if (idx < FIN * C1) {
        float w = W1[idx];
        __nv_bfloat16 hi = __float2bfloat16(w);
        g_whi[idx] = hi;
        g_wlo[idx] = __float2bfloat16(w - __bfloat162float(hi));
    } else if (idx < FIN * C1 + C1 * C1) {
        int j = idx - FIN * C1;           // k*128 + n
        int k = j >> 7, n = j & 127;
        float w = (n < HH) ? Wmu[k * HH + n] : Wls[k * HH + (n - HH)];
        __nv_bfloat16 hi = __float2bfloat16(w);
        g_wchi[j] = hi;
        g_wclo[j] = __float2bfloat16(w - __bfloat162float(hi));
    }
}

// ---------------- graph preprocessing ----------------
__global__ void k_deg_init() {
    int i = blockIdx.x * blockDim.x + threadIdx.x;
    if (i < NN) g_deg[i] = 1;   // self-loop
}

__global__ void k_deg_count(const int* __restrict__ ei) {
    int e = blockIdx.x * blockDim.x + threadIdx.x;
    if (e < EE) atomicAdd(&g_deg[ei[EE + e]], 1);
}

__global__ void k_scan_local() {
    __shared__ int sd[1024];
    int t = threadIdx.x;
    int i = blockIdx.x * 1024 + t;
    int v = (i < NN) ? (g_deg[i] - 1) : 0;
    sd[t] = v;
    __syncthreads();
#pragma unroll
    for (int off = 1; off < 1024; off <<= 1) {
        int x = (t >= off) ? sd[t - off] : 0;
        __syncthreads();
        sd[t] += x;
        __syncthreads();
    }
    if (i < NN) g_rowptr[i] = sd[t] - v;
    if (t == 1023) g_partial[blockIdx.x] = sd[1023];
}

__global__ void k_add_offsets() {
    __shared__ int base;
    int i = blockIdx.x * 256 + threadIdx.x;
    if (threadIdx.x == 0) {
        int nb = blockIdx.x >> 2;
        int s = 0;
        for (int b = 0; b < nb; b++) s += g_partial[b];
        base = s;
    }
    __syncthreads();
    if (i < NN) {
        int r = g_rowptr[i] + base;
        g_rowptr[i] = r;
        g_cursor[i] = r;
        g_dinv[i] = rsqrtf((float)g_deg[i]);
    }
    if (i == 0) g_rowptr[NN] = EE;
}

__global__ void k_scatter(const int* __restrict__ ei) {
    int e = blockIdx.x * blockDim.x + threadIdx.x;
    if (e < EE) {
        int s = ei[e];
        int d = ei[EE + e];
        int p = atomicAdd(&g_cursor[d], 1);
        g_srcs[p] = s;
    }
}

// ---------------- GEMM1 (mma.sync bf16, 3-term split) ---------------------
// EXACT copy of the R3 passing kernel (127 regs, no spill).
// t1[N,128] = x[N,512] @ W1[512,128];  CTA: 128x128, 8 warps (4x2), warp 32x64.
#define A_STRIDE 80      // bytes per A smem row (32 bf16 + pad)
#define W_STRIDE 272     // bytes per W smem row (128 bf16 + pad)

__global__ void __launch_bounds__(256, 2)
k_gemm1(const float* __restrict__ x) {
    __shared__ __align__(16) unsigned char sAh[128 * A_STRIDE];
    __shared__ __align__(16) unsigned char sAl[128 * A_STRIDE];
    __shared__ __align__(16) unsigned char sWh[32 * W_STRIDE];
    __shared__ __align__(16) unsigned char sWl[32 * W_STRIDE];

    const int tid = threadIdx.x;
    const int wid = tid >> 5, lane = tid & 31;
    const int warp_m = wid & 3;
    const int warp_n = wid >> 2;
    const int block_row = blockIdx.x * 128;

    const uint32_t sAh_u = smem_u32(sAh), sAl_u = smem_u32(sAl);
    const uint32_t sWh_u = smem_u32(sWh), sWl_u = smem_u32(sWl);

    float c[2][8][4];
#pragma unroll
    for (int mi = 0; mi < 2; mi++)
#pragma unroll
        for (int ni = 0; ni < 8; ni++)
#pragma unroll
            for (int q = 0; q < 4; q++) c[mi][ni][q] = 0.f;

    const int lrow = lane & 15;
    const int lcol16 = (lane >> 4) * 16;

    for (int kc = 0; kc < FIN / 32; kc++) {
#pragma unroll
        for (int l = 0; l < 4; l++) {
            int f4 = tid + 256 * l;
            int r = f4 >> 3, c4 = f4 & 7;
            int grow = block_row + r;
            float4 v = make_float4(0.f, 0.f, 0.f, 0.f);
            if (grow < NN) v = *(const float4*)&x[(size_t)grow * FIN + kc * 32 + c4 * 4];
            float hx = __bfloat162float(__float2bfloat16(v.x));
            float hy = __bfloat162float(__float2bfloat16(v.y));
            float hz = __bfloat162float(__float2bfloat16(v.z));
            float hw = __bfloat162float(__float2bfloat16(v.w));
            uint2 hi = make_uint2(bfpack(v.x, v.y), bfpack(v.z, v.w));
            uint2 lo = make_uint2(bfpack(v.x - hx, v.y - hy), bfpack(v.z - hz, v.w - hw));
            *(uint2*)(sAh + r * A_STRIDE + c4 * 8) = hi;
            *(uint2*)(sAl + r * A_STRIDE + c4 * 8) = lo;
        }
#pragma unroll
        for (int l = 0; l < 2; l++) {
            int u4 = tid + 256 * l;
            int r = u4 >> 4, c16 = u4 & 15;
            *(uint4*)(sWh + r * W_STRIDE + c16 * 16) =
                *(const uint4*)&g_whi[(size_t)(kc * 32 + r) * C1 + c16 * 8];
            *(uint4*)(sWl + r * W_STRIDE + c16 * 16) =
                *(const uint4*)&g_wlo[(size_t)(kc * 32 + r) * C1 + c16 * 8];
        }
        __syncthreads();

#pragma unroll
        for (int slab = 0; slab < 2; slab++) {
            uint32_t ah[2][4], al[2][4];
#pragma unroll
            for (int mi = 0; mi < 2; mi++) {
                uint32_t aoff = (uint32_t)(warp_m * 32 + mi * 16 + lrow) * A_STRIDE
                              + slab * 32 + lcol16;
                ldsm_x4(ah[mi][0], ah[mi][1], ah[mi][2], ah[mi][3], sAh_u + aoff);
                ldsm_x4(al[mi][0], al[mi][1], al[mi][2], al[mi][3], sAl_u + aoff);
            }
#pragma unroll
            for (int h = 0; h < 2; h++) {
                uint32_t bh[4][2], bl[4][2];
#pragma unroll
                for (int q = 0; q < 2; q++) {
                    uint32_t boff = (uint32_t)(slab * 16 + lrow) * W_STRIDE
                                  + (warp_n * 64 + h * 32 + q * 16) * 2 + lcol16;
                    ldsm_x4_t(bh[q * 2][0], bh[q * 2][1], bh[q * 2 + 1][0], bh[q * 2 + 1][1],
                              sWh_u + boff);
                    ldsm_x4_t(bl[q * 2][0], bl[q * 2][1], bl[q * 2 + 1][0], bl[q * 2 + 1][1],
                              sWl_u + boff);
                }
#pragma unroll
                for (int mi = 0; mi < 2; mi++)
#pragma unroll
                    for (int nn = 0; nn < 4; nn++) {
                        float* cc = c[mi][h * 4 + nn];
                        mma_bf16(cc, ah[mi], bh[nn]);
                        mma_bf16(cc, al[mi], bh[nn]);
                        mma_bf16(cc, ah[mi], bl[nn]);
                    }
            }
        }
        __syncthreads();
    }

    const int qrow = lane >> 2;
    const int qcol = (lane & 3) * 2;
#pragma unroll
    for (int mi = 0; mi < 2; mi++) {
        int r0 = block_row + warp_m * 32 + mi * 16 + qrow;
#pragma unroll
        for (int ni = 0; ni < 8; ni++) {
            int col = warp_n * 64 + ni * 8 + qcol;
            if (r0 < NN)
                *(float2*)&g_t1[(size_t)r0 * C1 + col] = make_float2(c[mi][ni][0], c[mi][ni][1]);
            if (r0 + 8 < NN)
                *(float2*)&g_t1[(size_t)(r0 + 8) * C1 + col] = make_float2(c[mi][ni][2], c[mi][ni][3]);
        }
    }
}

// ---------------- GEMM2b: p[N,128] = h[N,128] @ [Wmu|Wls][128,128] ---------
// Same body as k_gemm1; KD=128 literal; zero parameters (all globals).
// #pragma unroll 1 prevents the 4-trip K-loop from unrolling.
__global__ void __launch_bounds__(256, 2)
k_gemm2b() {
    __shared__ __align__(16) unsigned char sAh[128 * A_STRIDE];
    __shared__ __align__(16) unsigned char sAl[128 * A_STRIDE];
    __shared__ __align__(16) unsigned char sWh[32 * W_STRIDE];
    __shared__ __align__(16) unsigned char sWl[32 * W_STRIDE];

    const int tid = threadIdx.x;
    const int wid = tid >> 5, lane = tid & 31;
    const int warp_m = wid & 3;
    const int warp_n = wid >> 2;
    const int block_row = blockIdx.x * 128;

    const uint32_t sAh_u = smem_u32(sAh), sAl_u = smem_u32(sAl);
    const uint32_t sWh_u = smem_u32(sWh), sWl_u = smem_u32(sWl);

    float c[2][8][4];
#pragma unroll
    for (int mi = 0; mi < 2; mi++)
#pragma unroll
        for (int ni = 0; ni < 8; ni++)
#pragma unroll
            for (int q = 0; q < 4; q++) c[mi][ni][q] = 0.f;

    const int lrow = lane & 15;
    const int lcol16 = (lane >> 4) * 16;

#pragma unroll 1
    for (int kc = 0; kc < C1 / 32; kc++) {
#pragma unroll
        for (int l = 0; l < 4; l++) {
            int f4 = tid + 256 * l;
            int r = f4 >> 3, c4 = f4 & 7;
            int grow = block_row + r;
            float4 v = make_float4(0.f, 0.f, 0.f, 0.f);
            if (grow < NN) v = *(const float4*)&g_h[(size_t)grow * C1 + kc * 32 + c4 * 4];
            float hx = __bfloat162float(__float2bfloat16(v.x));
            float hy = __bfloat162float(__float2bfloat16(v.y));
            float hz = __bfloat162float(__float2bfloat16(v.z));
            float hw = __bfloat162float(__float2bfloat16(v.w));
            uint2 hi = make_uint2(bfpack(v.x, v.y), bfpack(v.z, v.w));
            uint2 lo = make_uint2(bfpack(v.x - hx, v.y - hy), bfpack(v.z - hz, v.w - hw));
            *(uint2*)(sAh + r * A_STRIDE + c4 * 8) = hi;
            *(uint2*)(sAl + r * A_STRIDE + c4 * 8) = lo;
        }
#pragma unroll
        for (int l = 0; l < 2; l++) {
            int u4 = tid + 256 * l;
            int r = u4 >> 4, c16 = u4 & 15;
            *(uint4*)(sWh + r * W_STRIDE + c16 * 16) =
                *(const uint4*)&g_wchi[(size_t)(kc * 32 + r) * C1 + c16 * 8];
            *(uint4*)(sWl + r * W_STRIDE + c16 * 16) =
                *(const uint4*)&g_wclo[(size_t)(kc * 32 + r) * C1 + c16 * 8];
        }
        __syncthreads();

#pragma unroll
        for (int slab = 0; slab < 2; slab++) {
            uint32_t ah[2][4], al[2][4];
#pragma unroll
            for (int mi = 0; mi < 2; mi++) {
                uint32_t aoff = (uint32_t)(warp_m * 32 + mi * 16 + lrow) * A_STRIDE
                              + slab * 32 + lcol16;
                ldsm_x4(ah[mi][0], ah[mi][1], ah[mi][2], ah[mi][3], sAh_u + aoff);
                ldsm_x4(al[mi][0], al[mi][1], al[mi][2], al[mi][3], sAl_u + aoff);
            }
#pragma unroll
            for (int h = 0; h < 2; h++) {
                uint32_t bh[4][2], bl[4][2];
#pragma unroll
                for (int q = 0; q < 2; q++) {
                    uint32_t boff = (uint32_t)(slab * 16 + lrow) * W_STRIDE
                                  + (warp_n * 64 + h * 32 + q * 16) * 2 + lcol16;
                    ldsm_x4_t(bh[q * 2][0], bh[q * 2][1], bh[q * 2 + 1][0], bh[q * 2 + 1][1],
                              sWh_u + boff);
                    ldsm_x4_t(bl[q * 2][0], bl[q * 2][1], bl[q * 2 + 1][0], bl[q * 2 + 1][1],
                              sWl_u + boff);
                }
#pragma unroll
                for (int mi = 0; mi < 2; mi++)
#pragma unroll
                    for (int nn = 0; nn < 4; nn++) {
                        float* cc = c[mi][h * 4 + nn];
                        mma_bf16(cc, ah[mi], bh[nn]);
                        mma_bf16(cc, al[mi], bh[nn]);
                        mma_bf16(cc, ah[mi], bl[nn]);
                    }
            }
        }
        __syncthreads();
    }

    const int qrow = lane >> 2;
    const int qcol = (lane & 3) * 2;
#pragma unroll
    for (int mi = 0; mi < 2; mi++) {
        int r0 = block_row + warp_m * 32 + mi * 16 + qrow;
#pragma unroll
        for (int ni = 0; ni < 8; ni++) {
            int col = warp_n * 64 + ni * 8 + qcol;
            if (r0 < NN)
                *(float2*)&g_p[(size_t)r0 * C1 + col] = make_float2(c[mi][ni][0], c[mi][ni][1]);
            if (r0 + 8 < NN)
                *(float2*)&g_p[(size_t)(r0 + 8) * C1 + col] = make_float2(c[mi][ni][2], c[mi][ni][3]);
        }
    }
}

// ---------------- aggregation pass 1: g_h = relu(agg(g_t1) + b1) ----------
__global__ void k_agg0(const float* __restrict__ bias) {
    int warp = threadIdx.x >> 5;
    int lane = threadIdx.x & 31;
    int i = blockIdx.x * 4 + warp;
    if (i >= NN) return;

    float di = g_dinv[i];
    float4 acc = *(const float4*)&g_t1[(size_t)i * C1 + lane * 4];
    float sw = di * di;
    acc.x *= sw; acc.y *= sw; acc.z *= sw; acc.w *= sw;

    int e  = g_rowptr[i];
    int e1 = g_rowptr[i + 1];
    for (; e + 1 < e1; e += 2) {
        int s0 = g_srcs[e], s1 = g_srcs[e + 1];
        float w0 = g_dinv[s0] * di;
        float w1 = g_dinv[s1] * di;
        float4 v0 = *(const float4*)&g_t1[(size_t)s0 * C1 + lane * 4];
        float4 v1 = *(const float4*)&g_t1[(size_t)s1 * C1 + lane * 4];
        acc.x = fmaf(v0.x, w0, fmaf(v1.x, w1, acc.x));
        acc.y = fmaf(v0.y, w0, fmaf(v1.y, w1, acc.y));
        acc.z = fmaf(v0.z, w0, fmaf(v1.z, w1, acc.z));
        acc.w = fmaf(v0.w, w0, fmaf(v1.w, w1, acc.w));
    }
    if (e < e1) {
        int s0 = g_srcs[e];
        float w0 = g_dinv[s0] * di;
        float4 v0 = *(const float4*)&g_t1[(size_t)s0 * C1 + lane * 4];
        acc.x = fmaf(v0.x, w0, acc.x);
        acc.y = fmaf(v0.y, w0, acc.y);
        acc.z = fmaf(v0.z, w0, acc.z);
        acc.w = fmaf(v0.w, w0, acc.w);
    }
    float4 b = *(const float4*)&bias[lane * 4];
    acc.x = fmaxf(acc.x + b.x, 0.f);
    acc.y = fmaxf(acc.y + b.y, 0.f);
    acc.z = fmaxf(acc.z + b.z, 0.f);
    acc.w = fmaxf(acc.w + b.w, 0.f);
    *(float4*)&g_h[(size_t)i * C1 + lane * 4] = acc;
}

// ---------------- aggregation pass 2: out = agg(g_p) + [bmu|bls] ----------
__global__ void k_agg_out(const float* __restrict__ bmu, const float* __restrict__ bls,
                          float* __restrict__ out) {
    int warp = threadIdx.x >> 5;
    int lane = threadIdx.x & 31;
    int i = blockIdx.x * 4 + warp;
    if (i >= NN) return;

    float di = g_dinv[i];
    float4 acc = *(const float4*)&g_p[(size_t)i * C1 + lane * 4];
    float sw = di * di;
    acc.x *= sw; acc.y *= sw; acc.z *= sw; acc.w *= sw;

    int e  = g_rowptr[i];
    int e1 = g_rowptr[i + 1];
    for (; e + 1 < e1; e += 2) {
        int s0 = g_srcs[e], s1 = g_srcs[e + 1];
        float w0 = g_dinv[s0] * di;
        float w1 = g_dinv[s1] * di;
        float4 v0 = *(const float4*)&g_p[(size_t)s0 * C1 + lane * 4];
        float4 v1 = *(const float4*)&g_p[(size_t)s1 * C1 + lane * 4];
        acc.x = fmaf(v0.x, w0, fmaf(v1.x, w1, acc.x));
        acc.y = fmaf(v0.y, w0, fmaf(v1.y, w1, acc.y));
        acc.z = fmaf(v0.z, w0, fmaf(v1.z, w1, acc.z));
        acc.w = fmaf(v0.w, w0, fmaf(v1.w, w1, acc.w));
    }
    if (e < e1) {
        int s0 = g_srcs[e];
        float w0 = g_dinv[s0] * di;
        float4 v0 = *(const float4*)&g_p[(size_t)s0 * C1 + lane * 4];
        acc.x = fmaf(v0.x, w0, acc.x);
        acc.y = fmaf(v0.y, w0, acc.y);
        acc.z = fmaf(v0.z, w0, acc.z);
        acc.w = fmaf(v0.w, w0, acc.w);
    }
    int col = lane * 4;            // 0..124 within the 128-wide row
    if (col < HH) {
        float4 b = *(const float4*)&bmu[col];
        acc.x += b.x; acc.y += b.y; acc.z += b.z; acc.w += b.w;
        *(float4*)&out[(size_t)i * HH + col] = acc;
    } else {
        float4 b = *(const float4*)&bls[col - HH];
        acc.x += b.x; acc.y += b.y; acc.z += b.z; acc.w += b.w;
        *(float4*)&out[(size_t)(NN + i) * HH + (col - HH)] = acc;
    }
}

// ---------------- launch ----------------
extern "C" void kernel_launch(void* const* d_in, const int* in_sizes, int n_in,
                              void* d_out, int out_size) {
    const float* x   = (const float*)d_in[0];
    const int*   ei  = (const int*)d_in[1];
    const float* W1  = (const float*)d_in[2];
    const float* b1  = (const float*)d_in[3];
    const float* Wmu = (const float*)d_in[4];
    const float* bmu = (const float*)d_in[5];
    const float* Wls = (const float*)d_in[6];
    const float* bls = (const float*)d_in[7];
    float* out = (float*)d_out;

    const int nb_n = (NN + 255) / 256;
    const int nb_e = (EE + 255) / 256;
    const int nb_s = (NN + 1023) / 1024;

    k_prep_w<<<(FIN * C1 + C1 * C1 + 255) / 256, 256>>>(W1, Wmu, Wls);
    k_deg_init<<<nb_n, 256>>>();
    k_deg_count<<<nb_e, 256>>>(ei);
    k_gemm1<<<(NN + 127) / 128, 256>>>(x);
    k_scan_local<<<nb_s, 1024>>>();
    k_add_offsets<<<nb_n, 256>>>();
    k_scatter<<<nb_e, 256>>>(ei);

    k_agg0<<<(NN + 3) / 4, 128>>>(b1);
    k_gemm2b<<<(NN + 127) / 128, 256>>>();
    k_agg_out<<<(NN + 3) / 4, 128>>>(bmu, bls, out);
}